// round 6
// baseline (speedup 1.0000x reference)
#include <cuda_runtime.h>
#include <cstdint>

// Problem constants
#define BB   2
#define SS   2048
#define DD   1024
#define HH   16
#define HD   64
#define QK_SCALE 0.125f      // 1/sqrt(64)

// ---------------- scratch (device globals; no allocation allowed) ----------
__device__ float g_qh[BB*HH*SS*HD];   // [B,H,S,HD]
__device__ float g_kh[BB*HH*SS*HD];
__device__ float g_vh[BB*HH*SS*HD];
__device__ float g_ao[BB*SS*DD];      // attention output, [B,S,D]

// ---------------------------------------------------------------------------
// helpers
// ---------------------------------------------------------------------------
__device__ __forceinline__ float to_tf32(float x) {
    float y;
    asm("cvt.rna.tf32.f32 %0, %1;" : "=f"(y) : "f"(x));
    return y;
}

__device__ __forceinline__ float4 to_tf32_4(float4 v) {
    v.x = to_tf32(v.x); v.y = to_tf32(v.y);
    v.z = to_tf32(v.z); v.w = to_tf32(v.w);
    return v;
}

// D = A(16x8,row) * B(8x8,col) + D, tf32 inputs, f32 accum
__device__ __forceinline__ void mma_tf32(float* d, const float* a, const float* b) {
    asm volatile(
        "mma.sync.aligned.m16n8k8.row.col.f32.tf32.tf32.f32 "
        "{%0,%1,%2,%3}, {%4,%5,%6,%7}, {%8,%9}, {%0,%1,%2,%3};"
        : "+f"(d[0]), "+f"(d[1]), "+f"(d[2]), "+f"(d[3])
        : "r"(__float_as_uint(a[0])), "r"(__float_as_uint(a[1])),
          "r"(__float_as_uint(a[2])), "r"(__float_as_uint(a[3])),
          "r"(__float_as_uint(b[0])), "r"(__float_as_uint(b[1])));
}

// ---------------------------------------------------------------------------
// Projection GEMM (TF32 mma): Y = X @ W^T + b   (unchanged from round 5)
// ---------------------------------------------------------------------------
#define PST 36   // smem row stride (floats)

template<int TGT>
__global__ __launch_bounds__(256) void proj_mma(const float* __restrict__ X,
                                                const float* __restrict__ W,
                                                const float* __restrict__ bias,
                                                float* __restrict__ Yp)
{
    __shared__ float As[128][PST];
    __shared__ float Bs[128][PST];

    const int m0   = blockIdx.y * 128;
    const int n0   = blockIdx.x * 128;
    const int tid  = threadIdx.x;
    const int wid  = tid >> 5;
    const int lane = tid & 31;
    const int wm   = wid >> 1;
    const int wn   = wid & 1;
    const int r    = lane >> 2;
    const int q    = lane & 3;

    float acc[2][8][4];
#pragma unroll
    for (int mt = 0; mt < 2; mt++)
#pragma unroll
        for (int j = 0; j < 8; j++)
#pragma unroll
            for (int c = 0; c < 4; c++) acc[mt][j][c] = 0.f;

    for (int k0 = 0; k0 < DD; k0 += 32) {
#pragma unroll
        for (int it = 0; it < 4; it++) {
            int lin = tid + it * 256;
            int row = lin >> 3;
            int c4  = lin & 7;
            float4 av = *(const float4*)&X[(size_t)(m0 + row) * DD + k0 + c4 * 4];
            *(float4*)&As[row][c4 * 4] = to_tf32_4(av);
            float4 bv = *(const float4*)&W[(size_t)(n0 + row) * DD + k0 + c4 * 4];
            *(float4*)&Bs[row][c4 * 4] = to_tf32_4(bv);
        }
        __syncthreads();

#pragma unroll
        for (int ks = 0; ks < 4; ks++) {
            float a[2][4], b[8][2];
#pragma unroll
            for (int mt = 0; mt < 2; mt++) {
                int row = wm * 32 + mt * 16 + r;
                a[mt][0] = As[row][ks * 8 + q];
                a[mt][1] = As[row + 8][ks * 8 + q];
                a[mt][2] = As[row][ks * 8 + q + 4];
                a[mt][3] = As[row + 8][ks * 8 + q + 4];
            }
#pragma unroll
            for (int j = 0; j < 8; j++) {
                int row = wn * 64 + j * 8 + r;
                b[j][0] = Bs[row][ks * 8 + q];
                b[j][1] = Bs[row][ks * 8 + q + 4];
            }
#pragma unroll
            for (int mt = 0; mt < 2; mt++)
#pragma unroll
                for (int j = 0; j < 8; j++)
                    mma_tf32(acc[mt][j], a[mt], b[j]);
        }
        __syncthreads();
    }

    float* out = (TGT == 0) ? g_qh : (TGT == 1) ? g_kh : (TGT == 2) ? g_vh : Yp;

#pragma unroll
    for (int mt = 0; mt < 2; mt++) {
#pragma unroll
        for (int j = 0; j < 8; j++) {
            int n  = n0 + wn * 64 + j * 8 + 2 * q;
            float b0 = bias[n], b1 = bias[n + 1];
#pragma unroll
            for (int half = 0; half < 2; half++) {
                int m = m0 + wm * 32 + mt * 16 + r + half * 8;
                float y0 = acc[mt][j][half * 2 + 0] + b0;
                float y1 = acc[mt][j][half * 2 + 1] + b1;
                if (TGT < 3) {
                    int bb = m >> 11, s = m & 2047;
                    int h  = n >> 6,  d = n & 63;
                    float* dst = out + (((size_t)bb * HH + h) * SS + s) * HD + d;
                    *(float2*)dst = make_float2(y0, y1);
                } else {
                    *(float2*)&out[(size_t)m * DD + n] = make_float2(y0, y1);
                }
            }
        }
    }
}

// ---------------------------------------------------------------------------
// Flash attention v2 (TF32 mma):
//   - Q fragments register-resident (staged through Ks buffer once)
//   - P register-resident: C-frag -> A-frag via quad shuffles (no Ps smem)
//   - K stored with column-pair permutation -> B-frag loads are LDS.64
//   - smem: Ks + Vs only (static, 34.8 KB)
// Grid (S/64, H, B), 128 threads (4 warps), warp owns 16 query rows.
// ---------------------------------------------------------------------------
#define FS 68

__global__ __launch_bounds__(128) void flash_mma()
{
    __shared__ float Ks[64 * FS];
    __shared__ float Vs[64 * FS];

    const int q0   = blockIdx.x * 64;
    const int h    = blockIdx.y;
    const int b    = blockIdx.z;
    const int tid  = threadIdx.x;
    const int wid  = tid >> 5;
    const int lane = tid & 31;
    const int r    = lane >> 2;     // quad id 0..7  (lane = 4r + q)
    const int q    = lane & 3;      // 0..3
    const int wrow = wid * 16;

    const float* Qb = g_qh + ((size_t)(b * HH + h) * SS) * HD;
    const float* Kb = g_kh + ((size_t)(b * HH + h) * SS) * HD;
    const float* Vb = g_vh + ((size_t)(b * HH + h) * SS) * HD;

    // ---- stage Q (scaled, tf32) into Ks buffer, extract fragments to regs
#pragma unroll
    for (int it = 0; it < 8; it++) {
        int lin = tid + it * 128;
        int row = lin >> 4;
        int c4  = lin & 15;
        float4 v = *(const float4*)&Qb[(size_t)(q0 + row) * HD + c4 * 4];
        v.x *= QK_SCALE; v.y *= QK_SCALE; v.z *= QK_SCALE; v.w *= QK_SCALE;
        *(float4*)&Ks[row * FS + c4 * 4] = to_tf32_4(v);
    }
    __syncthreads();

    float qf[8][4];
#pragma unroll
    for (int ks = 0; ks < 8; ks++) {
        qf[ks][0] = Ks[(wrow + r) * FS + ks * 8 + q];
        qf[ks][1] = Ks[(wrow + r + 8) * FS + ks * 8 + q];
        qf[ks][2] = Ks[(wrow + r) * FS + ks * 8 + q + 4];
        qf[ks][3] = Ks[(wrow + r + 8) * FS + ks * 8 + q + 4];
    }
    __syncthreads();

    float o[8][4];
#pragma unroll
    for (int j = 0; j < 8; j++)
#pragma unroll
        for (int c = 0; c < 4; c++) o[j][c] = 0.f;
    float m0_ = -1e30f, m1_ = -1e30f, l0 = 0.f, l1 = 0.f;

    for (int kt = 0; kt < SS / 64; kt++) {
        const float* Kt = Kb + (size_t)(kt * 64) * HD;
        const float* Vt = Vb + (size_t)(kt * 64) * HD;

        // K: permuted columns (within each 8-group: k<4 -> 2k, k>=4 -> 2(k-4)+1)
        // V: plain layout.
#pragma unroll
        for (int it = 0; it < 8; it++) {
            int lin = tid + it * 128;
            int row = lin >> 4;
            int c4  = lin & 15;
            float4 kv = to_tf32_4(*(const float4*)&Kt[(size_t)row * HD + c4 * 4]);
            int g   = c4 >> 1;
            int odd = c4 & 1;
            float* kb = &Ks[row * FS + g * 8 + odd];
            kb[0] = kv.x; kb[2] = kv.y; kb[4] = kv.z; kb[6] = kv.w;
            *(float4*)&Vs[row * FS + c4 * 4] =
                to_tf32_4(*(const float4*)&Vt[(size_t)row * HD + c4 * 4]);
        }
        __syncthreads();

        // ---- S = Q K^T
        float s[8][4];
#pragma unroll
        for (int j = 0; j < 8; j++)
#pragma unroll
            for (int c = 0; c < 4; c++) s[j][c] = 0.f;

#pragma unroll
        for (int ks = 0; ks < 8; ks++) {
#pragma unroll
            for (int j = 0; j < 8; j++) {
                float2 bp = *(const float2*)&Ks[(j * 8 + r) * FS + ks * 8 + 2 * q];
                float bfr[2] = { bp.x, bp.y };
                mma_tf32(s[j], qf[ks], bfr);
            }
        }

        // ---- online softmax (rows wrow+r and wrow+r+8; reduce over quad)
        float t0 = -1e30f, t1 = -1e30f;
#pragma unroll
        for (int j = 0; j < 8; j++) {
            t0 = fmaxf(t0, fmaxf(s[j][0], s[j][1]));
            t1 = fmaxf(t1, fmaxf(s[j][2], s[j][3]));
        }
#pragma unroll
        for (int msk = 1; msk <= 2; msk <<= 1) {
            t0 = fmaxf(t0, __shfl_xor_sync(0xffffffffu, t0, msk));
            t1 = fmaxf(t1, __shfl_xor_sync(0xffffffffu, t1, msk));
        }
        float nm0 = fmaxf(m0_, t0), nm1 = fmaxf(m1_, t1);
        float corr0 = __expf(m0_ - nm0), corr1 = __expf(m1_ - nm1);
        m0_ = nm0; m1_ = nm1;

        float rs0 = 0.f, rs1 = 0.f;
#pragma unroll
        for (int j = 0; j < 8; j++) {
            s[j][0] = __expf(s[j][0] - nm0);
            s[j][1] = __expf(s[j][1] - nm0);
            s[j][2] = __expf(s[j][2] - nm1);
            s[j][3] = __expf(s[j][3] - nm1);
            rs0 += s[j][0] + s[j][1];
            rs1 += s[j][2] + s[j][3];
        }
#pragma unroll
        for (int msk = 1; msk <= 2; msk <<= 1) {
            rs0 += __shfl_xor_sync(0xffffffffu, rs0, msk);
            rs1 += __shfl_xor_sync(0xffffffffu, rs1, msk);
        }
        l0 = l0 * corr0 + rs0;
        l1 = l1 * corr1 + rs1;

        // tf32-round P in place (before shuffles)
#pragma unroll
        for (int j = 0; j < 8; j++) {
            s[j][0] = to_tf32(s[j][0]);
            s[j][1] = to_tf32(s[j][1]);
            s[j][2] = to_tf32(s[j][2]);
            s[j][3] = to_tf32(s[j][3]);
        }

        // rescale O
#pragma unroll
        for (int j = 0; j < 8; j++) {
            o[j][0] *= corr0; o[j][1] *= corr0;
            o[j][2] *= corr1; o[j][3] *= corr1;
        }

        // ---- O += P @ V : C-frag -> A-frag via quad shuffles
        const int qh = q >> 1;
        const int qb = q & 1;
#pragma unroll
        for (int ks = 0; ks < 8; ks++) {
            float v00 = __shfl_sync(0xffffffffu, s[ks][0], qh, 4);
            float v01 = __shfl_sync(0xffffffffu, s[ks][1], qh, 4);
            float v02 = __shfl_sync(0xffffffffu, s[ks][2], qh, 4);
            float v03 = __shfl_sync(0xffffffffu, s[ks][3], qh, 4);
            float v10 = __shfl_sync(0xffffffffu, s[ks][0], qh + 2, 4);
            float v11 = __shfl_sync(0xffffffffu, s[ks][1], qh + 2, 4);
            float v12 = __shfl_sync(0xffffffffu, s[ks][2], qh + 2, 4);
            float v13 = __shfl_sync(0xffffffffu, s[ks][3], qh + 2, 4);
            float a[4];
            a[0] = qb ? v01 : v00;   // row r,   k = ks*8+q
            a[1] = qb ? v03 : v02;   // row r+8, k = ks*8+q
            a[2] = qb ? v11 : v10;   // row r,   k = ks*8+q+4
            a[3] = qb ? v13 : v12;   // row r+8, k = ks*8+q+4
#pragma unroll
            for (int j = 0; j < 8; j++) {
                float bfr[2];
                bfr[0] = Vs[(ks * 8 + q) * FS + j * 8 + r];
                bfr[1] = Vs[(ks * 8 + q + 4) * FS + j * 8 + r];
                mma_tf32(o[j], a, bfr);
            }
        }
        __syncthreads();   // all Ks/Vs reads done before next tile overwrite
    }

    // epilogue: normalize, write g_ao [B,S,D] (D col = h*64 + n)
    float inv0 = 1.f / l0, inv1 = 1.f / l1;
#pragma unroll
    for (int j = 0; j < 8; j++) {
        int col = h * HD + j * 8 + 2 * q;
        int s0  = q0 + wrow + r;
        float* d0 = g_ao + ((size_t)b * SS + s0) * DD + col;
        *(float2*)d0 = make_float2(o[j][0] * inv0, o[j][1] * inv0);
        float* d1 = g_ao + ((size_t)b * SS + s0 + 8) * DD + col;
        *(float2*)d1 = make_float2(o[j][2] * inv1, o[j][3] * inv1);
    }
}

// ---------------------------------------------------------------------------
extern "C" void kernel_launch(void* const* d_in, const int* in_sizes, int n_in,
                              void* d_out, int out_size)
{
    const float* q  = (const float*)d_in[0];
    const float* k  = (const float*)d_in[1];
    const float* v  = (const float*)d_in[2];
    const float* Wq = (const float*)d_in[3];
    const float* bq = (const float*)d_in[4];
    const float* Wk = (const float*)d_in[5];
    const float* bk = (const float*)d_in[6];
    const float* Wv = (const float*)d_in[7];
    const float* bv = (const float*)d_in[8];
    const float* Wo = (const float*)d_in[9];
    const float* bo = (const float*)d_in[10];
    float* out = (float*)d_out;

    dim3 pgrid(DD / 128, (BB * SS) / 128);   // (8, 32)
    proj_mma<0><<<pgrid, 256>>>(q, Wq, bq, nullptr);
    proj_mma<1><<<pgrid, 256>>>(k, Wk, bk, nullptr);
    proj_mma<2><<<pgrid, 256>>>(v, Wv, bv, nullptr);

    flash_mma<<<dim3(SS / 64, HH, BB), 128>>>();

    void* p_ao = nullptr;
    cudaGetSymbolAddress(&p_ao, g_ao);
    proj_mma<3><<<pgrid, 256>>>((const float*)p_ao, Wo, bo, out);
}

// round 9
// speedup vs baseline: 1.0616x; 1.0616x over previous
#include <cuda_runtime.h>
#include <cstdint>

// Problem constants
#define BB   2
#define SS   2048
#define DD   1024
#define HH   16
#define HD   64
#define QK_SCALE 0.125f      // 1/sqrt(64)

// ---------------- scratch (device globals; no allocation allowed) ----------
__device__ float g_qh[BB*HH*SS*HD];   // [B,H,S,HD]
__device__ float g_kh[BB*HH*SS*HD];
__device__ float g_vh[BB*HH*SS*HD];
__device__ float g_ao[BB*SS*DD];      // attention output, [B,S,D]

// ---------------------------------------------------------------------------
// helpers
// ---------------------------------------------------------------------------
__device__ __forceinline__ float to_tf32(float x) {
    float y;
    asm("cvt.rna.tf32.f32 %0, %1;" : "=f"(y) : "f"(x));
    return y;
}
__device__ __forceinline__ float4 to_tf32_4(float4 v) {
    v.x = to_tf32(v.x); v.y = to_tf32(v.y);
    v.z = to_tf32(v.z); v.w = to_tf32(v.w);
    return v;
}

// D = A(16x8,row) * B(8x8,col) + D, tf32 inputs, f32 accum
__device__ __forceinline__ void mma_tf32(float* d, const float* a, const float* b) {
    asm volatile(
        "mma.sync.aligned.m16n8k8.row.col.f32.tf32.tf32.f32 "
        "{%0,%1,%2,%3}, {%4,%5,%6,%7}, {%8,%9}, {%0,%1,%2,%3};"
        : "+f"(d[0]), "+f"(d[1]), "+f"(d[2]), "+f"(d[3])
        : "r"(__float_as_uint(a[0])), "r"(__float_as_uint(a[1])),
          "r"(__float_as_uint(a[2])), "r"(__float_as_uint(a[3])),
          "r"(__float_as_uint(b[0])), "r"(__float_as_uint(b[1])));
}

// ---------------------------------------------------------------------------
// Projection GEMM (TF32 mma): Y = X @ W^T + b   (unchanged, known-good)
// ---------------------------------------------------------------------------
#define PST 36

template<int TGT>
__global__ __launch_bounds__(256) void proj_mma(const float* __restrict__ X,
                                                const float* __restrict__ W,
                                                const float* __restrict__ bias,
                                                float* __restrict__ Yp)
{
    __shared__ float As[128][PST];
    __shared__ float Bs[128][PST];

    const int m0   = blockIdx.y * 128;
    const int n0   = blockIdx.x * 128;
    const int tid  = threadIdx.x;
    const int wid  = tid >> 5;
    const int lane = tid & 31;
    const int wm   = wid >> 1;
    const int wn   = wid & 1;
    const int r    = lane >> 2;
    const int q    = lane & 3;

    float acc[2][8][4];
#pragma unroll
    for (int mt = 0; mt < 2; mt++)
#pragma unroll
        for (int j = 0; j < 8; j++)
#pragma unroll
            for (int c = 0; c < 4; c++) acc[mt][j][c] = 0.f;

    for (int k0 = 0; k0 < DD; k0 += 32) {
#pragma unroll
        for (int it = 0; it < 4; it++) {
            int lin = tid + it * 256;
            int row = lin >> 3;
            int c4  = lin & 7;
            float4 av = *(const float4*)&X[(size_t)(m0 + row) * DD + k0 + c4 * 4];
            *(float4*)&As[row][c4 * 4] = to_tf32_4(av);
            float4 bv = *(const float4*)&W[(size_t)(n0 + row) * DD + k0 + c4 * 4];
            *(float4*)&Bs[row][c4 * 4] = to_tf32_4(bv);
        }
        __syncthreads();

#pragma unroll
        for (int ks = 0; ks < 4; ks++) {
            float a[2][4], b[8][2];
#pragma unroll
            for (int mt = 0; mt < 2; mt++) {
                int row = wm * 32 + mt * 16 + r;
                a[mt][0] = As[row][ks * 8 + q];
                a[mt][1] = As[row + 8][ks * 8 + q];
                a[mt][2] = As[row][ks * 8 + q + 4];
                a[mt][3] = As[row + 8][ks * 8 + q + 4];
            }
#pragma unroll
            for (int j = 0; j < 8; j++) {
                int row = wn * 64 + j * 8 + r;
                b[j][0] = Bs[row][ks * 8 + q];
                b[j][1] = Bs[row][ks * 8 + q + 4];
            }
#pragma unroll
            for (int mt = 0; mt < 2; mt++)
#pragma unroll
                for (int j = 0; j < 8; j++)
                    mma_tf32(acc[mt][j], a[mt], b[j]);
        }
        __syncthreads();
    }

    float* out = (TGT == 0) ? g_qh : (TGT == 1) ? g_kh : (TGT == 2) ? g_vh : Yp;

#pragma unroll
    for (int mt = 0; mt < 2; mt++) {
#pragma unroll
        for (int j = 0; j < 8; j++) {
            int n  = n0 + wn * 64 + j * 8 + 2 * q;
            float b0 = bias[n], b1 = bias[n + 1];
#pragma unroll
            for (int half = 0; half < 2; half++) {
                int m = m0 + wm * 32 + mt * 16 + r + half * 8;
                float y0 = acc[mt][j][half * 2 + 0] + b0;
                float y1 = acc[mt][j][half * 2 + 1] + b1;
                if (TGT < 3) {
                    int bb = m >> 11, s = m & 2047;
                    int h  = n >> 6,  d = n & 63;
                    float* dst = out + (((size_t)bb * HH + h) * SS + s) * HD + d;
                    *(float2*)dst = make_float2(y0, y1);
                } else {
                    *(float2*)&out[(size_t)m * DD + n] = make_float2(y0, y1);
                }
            }
        }
    }
}

// ---------------------------------------------------------------------------
// Flash attention v3 (mma.sync tf32):
//   = R5 structure + Q fragments in registers + split Ks/Vs/Ps buffers
//   - P is intra-warp only (write->read by same warp): no sync needed
//   - 2 syncthreads per tile (load, end) instead of R5's 3
//   - smem 52.2KB -> 4 CTAs/SM; __launch_bounds__(128,4)
// Grid (S/64, H, B), 128 threads (4 warps), warp owns 16 query rows.
// ---------------------------------------------------------------------------
#define FS 68
#define FLASH_SMEM (3 * 64 * FS * 4)

__global__ __launch_bounds__(128, 4) void flash_mma()
{
    extern __shared__ float sm[];
    float* Ks = sm;
    float* Vs = sm + 64 * FS;
    float* Ps = sm + 2 * 64 * FS;

    const int q0   = blockIdx.x * 64;
    const int h    = blockIdx.y;
    const int b    = blockIdx.z;
    const int tid  = threadIdx.x;
    const int wid  = tid >> 5;
    const int lane = tid & 31;
    const int r    = lane >> 2;
    const int q    = lane & 3;
    const int wrow = wid * 16;

    const float* Qb = g_qh + ((size_t)(b * HH + h) * SS) * HD;
    const float* Kb = g_kh + ((size_t)(b * HH + h) * SS) * HD;
    const float* Vb = g_vh + ((size_t)(b * HH + h) * SS) * HD;

    // stage Q (scaled, tf32) through Ks, extract A-fragments to registers
#pragma unroll
    for (int it = 0; it < 8; it++) {
        int lin = tid + it * 128;
        int row = lin >> 4;
        int c4  = lin & 15;
        float4 v = *(const float4*)&Qb[(size_t)(q0 + row) * HD + c4 * 4];
        v.x *= QK_SCALE; v.y *= QK_SCALE; v.z *= QK_SCALE; v.w *= QK_SCALE;
        *(float4*)&Ks[row * FS + c4 * 4] = to_tf32_4(v);
    }
    __syncthreads();

    float qf[8][4];
#pragma unroll
    for (int ks = 0; ks < 8; ks++) {
        qf[ks][0] = Ks[(wrow + r) * FS + ks * 8 + q];
        qf[ks][1] = Ks[(wrow + r + 8) * FS + ks * 8 + q];
        qf[ks][2] = Ks[(wrow + r) * FS + ks * 8 + q + 4];
        qf[ks][3] = Ks[(wrow + r + 8) * FS + ks * 8 + q + 4];
    }
    __syncthreads();

    float o[8][4];
#pragma unroll
    for (int j = 0; j < 8; j++)
#pragma unroll
        for (int c = 0; c < 4; c++) o[j][c] = 0.f;
    float m0_ = -1e30f, m1_ = -1e30f, l0 = 0.f, l1 = 0.f;

    for (int kt = 0; kt < SS / 64; kt++) {
        const float* Kt = Kb + (size_t)(kt * 64) * HD;
        const float* Vt = Vb + (size_t)(kt * 64) * HD;

        // load K and V tiles (plain layout, STS.128)
#pragma unroll
        for (int it = 0; it < 8; it++) {
            int lin = tid + it * 128;
            int row = lin >> 4;
            int c4  = lin & 15;
            *(float4*)&Ks[row * FS + c4 * 4] =
                to_tf32_4(*(const float4*)&Kt[(size_t)row * HD + c4 * 4]);
            *(float4*)&Vs[row * FS + c4 * 4] =
                to_tf32_4(*(const float4*)&Vt[(size_t)row * HD + c4 * 4]);
        }
        __syncthreads();

        // ---- S = Q K^T (Q from registers)
        float s[8][4];
#pragma unroll
        for (int j = 0; j < 8; j++)
#pragma unroll
            for (int c = 0; c < 4; c++) s[j][c] = 0.f;

#pragma unroll
        for (int ks = 0; ks < 8; ks++) {
#pragma unroll
            for (int j = 0; j < 8; j++) {
                float bfr[2];
                bfr[0] = Ks[(j * 8 + r) * FS + ks * 8 + q];
                bfr[1] = Ks[(j * 8 + r) * FS + ks * 8 + q + 4];
                mma_tf32(s[j], qf[ks], bfr);
            }
        }

        // ---- online softmax (rows wrow+r and wrow+r+8; quad reduce)
        float t0 = -1e30f, t1 = -1e30f;
#pragma unroll
        for (int j = 0; j < 8; j++) {
            t0 = fmaxf(t0, fmaxf(s[j][0], s[j][1]));
            t1 = fmaxf(t1, fmaxf(s[j][2], s[j][3]));
        }
#pragma unroll
        for (int msk = 1; msk <= 2; msk <<= 1) {
            t0 = fmaxf(t0, __shfl_xor_sync(0xffffffffu, t0, msk));
            t1 = fmaxf(t1, __shfl_xor_sync(0xffffffffu, t1, msk));
        }
        float nm0 = fmaxf(m0_, t0), nm1 = fmaxf(m1_, t1);
        float corr0 = __expf(m0_ - nm0), corr1 = __expf(m1_ - nm1);
        m0_ = nm0; m1_ = nm1;

        float rs0 = 0.f, rs1 = 0.f;
#pragma unroll
        for (int j = 0; j < 8; j++) {
            s[j][0] = __expf(s[j][0] - nm0);
            s[j][1] = __expf(s[j][1] - nm0);
            s[j][2] = __expf(s[j][2] - nm1);
            s[j][3] = __expf(s[j][3] - nm1);
            rs0 += s[j][0] + s[j][1];
            rs1 += s[j][2] + s[j][3];
        }
#pragma unroll
        for (int msk = 1; msk <= 2; msk <<= 1) {
            rs0 += __shfl_xor_sync(0xffffffffu, rs0, msk);
            rs1 += __shfl_xor_sync(0xffffffffu, rs1, msk);
        }
        l0 = l0 * corr0 + rs0;
        l1 = l1 * corr1 + rs1;

        // stage P (tf32) to own-warp rows of Ps; no sync needed (intra-warp)
#pragma unroll
        for (int j = 0; j < 8; j++) {
            *(float2*)&Ps[(wrow + r) * FS + j * 8 + 2 * q] =
                make_float2(to_tf32(s[j][0]), to_tf32(s[j][1]));
            *(float2*)&Ps[(wrow + r + 8) * FS + j * 8 + 2 * q] =
                make_float2(to_tf32(s[j][2]), to_tf32(s[j][3]));
        }

        // rescale O
#pragma unroll
        for (int j = 0; j < 8; j++) {
            o[j][0] *= corr0; o[j][1] *= corr0;
            o[j][2] *= corr1; o[j][3] *= corr1;
        }
        __syncwarp();

        // ---- O += P @ V
#pragma unroll
        for (int ks = 0; ks < 8; ks++) {
            float a[4];
            a[0] = Ps[(wrow + r) * FS + ks * 8 + q];
            a[1] = Ps[(wrow + r + 8) * FS + ks * 8 + q];
            a[2] = Ps[(wrow + r) * FS + ks * 8 + q + 4];
            a[3] = Ps[(wrow + r + 8) * FS + ks * 8 + q + 4];
#pragma unroll
            for (int j = 0; j < 8; j++) {
                float bfr[2];
                bfr[0] = Vs[(ks * 8 + q) * FS + j * 8 + r];
                bfr[1] = Vs[(ks * 8 + q + 4) * FS + j * 8 + r];
                mma_tf32(o[j], a, bfr);
            }
        }
        __syncthreads();   // Ks/Vs reads done before next tile load
    }

    // epilogue: normalize, write g_ao [B,S,D] (D col = h*64 + n)
    float inv0 = 1.f / l0, inv1 = 1.f / l1;
#pragma unroll
    for (int j = 0; j < 8; j++) {
        int col = h * HD + j * 8 + 2 * q;
        int s0  = q0 + wrow + r;
        float* d0 = g_ao + ((size_t)b * SS + s0) * DD + col;
        *(float2*)d0 = make_float2(o[j][0] * inv0, o[j][1] * inv0);
        float* d1 = g_ao + ((size_t)b * SS + s0 + 8) * DD + col;
        *(float2*)d1 = make_float2(o[j][2] * inv1, o[j][3] * inv1);
    }
}

// ---------------------------------------------------------------------------
extern "C" void kernel_launch(void* const* d_in, const int* in_sizes, int n_in,
                              void* d_out, int out_size)
{
    const float* q  = (const float*)d_in[0];
    const float* k  = (const float*)d_in[1];
    const float* v  = (const float*)d_in[2];
    const float* Wq = (const float*)d_in[3];
    const float* bq = (const float*)d_in[4];
    const float* Wk = (const float*)d_in[5];
    const float* bk = (const float*)d_in[6];
    const float* Wv = (const float*)d_in[7];
    const float* bv = (const float*)d_in[8];
    const float* Wo = (const float*)d_in[9];
    const float* bo = (const float*)d_in[10];
    float* out = (float*)d_out;

    cudaFuncSetAttribute(flash_mma,
                         cudaFuncAttributeMaxDynamicSharedMemorySize, FLASH_SMEM);

    dim3 pgrid(DD / 128, (BB * SS) / 128);   // (8, 32)
    proj_mma<0><<<pgrid, 256>>>(q, Wq, bq, nullptr);
    proj_mma<1><<<pgrid, 256>>>(k, Wk, bk, nullptr);
    proj_mma<2><<<pgrid, 256>>>(v, Wv, bv, nullptr);

    flash_mma<<<dim3(SS / 64, HH, BB), 128, FLASH_SMEM>>>();

    void* p_ao = nullptr;
    cudaGetSymbolAddress(&p_ao, g_ao);
    proj_mma<3><<<pgrid, 256>>>((const float*)p_ao, Wo, bo, out);
}

// round 10
// speedup vs baseline: 1.1439x; 1.0776x over previous
#include <cuda_runtime.h>
#include <cstdint>

// Problem constants
#define BB   2
#define SS   2048
#define DD   1024
#define HH   16
#define HD   64
#define QK_SCALE 0.125f      // 1/sqrt(64)

// ---------------- scratch (device globals; no allocation allowed) ----------
__device__ float g_qh[BB*HH*SS*HD];   // [B,H,S,HD]
__device__ float g_kh[BB*HH*SS*HD];
__device__ float g_vh[BB*HH*SS*HD];
__device__ float g_ao[BB*SS*DD];      // attention output, [B,S,D]

// ---------------------------------------------------------------------------
// helpers
// ---------------------------------------------------------------------------
__device__ __forceinline__ float to_tf32(float x) {
    float y;
    asm("cvt.rna.tf32.f32 %0, %1;" : "=f"(y) : "f"(x));
    return y;
}
__device__ __forceinline__ float4 to_tf32_4(float4 v) {
    v.x = to_tf32(v.x); v.y = to_tf32(v.y);
    v.z = to_tf32(v.z); v.w = to_tf32(v.w);
    return v;
}

// D = A(16x8,row) * B(8x8,col) + D, tf32 inputs, f32 accum
__device__ __forceinline__ void mma_tf32(float* d, const float* a, const float* b) {
    asm volatile(
        "mma.sync.aligned.m16n8k8.row.col.f32.tf32.tf32.f32 "
        "{%0,%1,%2,%3}, {%4,%5,%6,%7}, {%8,%9}, {%0,%1,%2,%3};"
        : "+f"(d[0]), "+f"(d[1]), "+f"(d[2]), "+f"(d[3])
        : "r"(__float_as_uint(a[0])), "r"(__float_as_uint(a[1])),
          "r"(__float_as_uint(a[2])), "r"(__float_as_uint(a[3])),
          "r"(__float_as_uint(b[0])), "r"(__float_as_uint(b[1])));
}

// ---------------------------------------------------------------------------
// Projection GEMM (TF32 mma): Y = X @ W^T + b   (unchanged, known-good)
// ---------------------------------------------------------------------------
#define PST 36

template<int TGT>
__global__ __launch_bounds__(256) void proj_mma(const float* __restrict__ X,
                                                const float* __restrict__ W,
                                                const float* __restrict__ bias,
                                                float* __restrict__ Yp)
{
    __shared__ float As[128][PST];
    __shared__ float Bs[128][PST];

    const int m0   = blockIdx.y * 128;
    const int n0   = blockIdx.x * 128;
    const int tid  = threadIdx.x;
    const int wid  = tid >> 5;
    const int lane = tid & 31;
    const int wm   = wid >> 1;
    const int wn   = wid & 1;
    const int r    = lane >> 2;
    const int q    = lane & 3;

    float acc[2][8][4];
#pragma unroll
    for (int mt = 0; mt < 2; mt++)
#pragma unroll
        for (int j = 0; j < 8; j++)
#pragma unroll
            for (int c = 0; c < 4; c++) acc[mt][j][c] = 0.f;

    for (int k0 = 0; k0 < DD; k0 += 32) {
#pragma unroll
        for (int it = 0; it < 4; it++) {
            int lin = tid + it * 256;
            int row = lin >> 3;
            int c4  = lin & 7;
            float4 av = *(const float4*)&X[(size_t)(m0 + row) * DD + k0 + c4 * 4];
            *(float4*)&As[row][c4 * 4] = to_tf32_4(av);
            float4 bv = *(const float4*)&W[(size_t)(n0 + row) * DD + k0 + c4 * 4];
            *(float4*)&Bs[row][c4 * 4] = to_tf32_4(bv);
        }
        __syncthreads();

#pragma unroll
        for (int ks = 0; ks < 4; ks++) {
            float a[2][4], b[8][2];
#pragma unroll
            for (int mt = 0; mt < 2; mt++) {
                int row = wm * 32 + mt * 16 + r;
                a[mt][0] = As[row][ks * 8 + q];
                a[mt][1] = As[row + 8][ks * 8 + q];
                a[mt][2] = As[row][ks * 8 + q + 4];
                a[mt][3] = As[row + 8][ks * 8 + q + 4];
            }
#pragma unroll
            for (int j = 0; j < 8; j++) {
                int row = wn * 64 + j * 8 + r;
                b[j][0] = Bs[row][ks * 8 + q];
                b[j][1] = Bs[row][ks * 8 + q + 4];
            }
#pragma unroll
            for (int mt = 0; mt < 2; mt++)
#pragma unroll
                for (int j = 0; j < 8; j++)
                    mma_tf32(acc[mt][j], a[mt], b[j]);
        }
        __syncthreads();
    }

    float* out = (TGT == 0) ? g_qh : (TGT == 1) ? g_kh : (TGT == 2) ? g_vh : Yp;

#pragma unroll
    for (int mt = 0; mt < 2; mt++) {
#pragma unroll
        for (int j = 0; j < 8; j++) {
            int n  = n0 + wn * 64 + j * 8 + 2 * q;
            float b0 = bias[n], b1 = bias[n + 1];
#pragma unroll
            for (int half = 0; half < 2; half++) {
                int m = m0 + wm * 32 + mt * 16 + r + half * 8;
                float y0 = acc[mt][j][half * 2 + 0] + b0;
                float y1 = acc[mt][j][half * 2 + 1] + b1;
                if (TGT < 3) {
                    int bb = m >> 11, s = m & 2047;
                    int h  = n >> 6,  d = n & 63;
                    float* dst = out + (((size_t)bb * HH + h) * SS + s) * HD + d;
                    *(float2*)dst = make_float2(y0, y1);
                } else {
                    *(float2*)&out[(size_t)m * DD + n] = make_float2(y0, y1);
                }
            }
        }
    }
}

// ---------------------------------------------------------------------------
// Flash attention v4 (mma.sync tf32):
//   Warp owns 32 query rows (2 x m16 tiles) -> K/V B-fragment LDS amortized
//   over 2x the work (~1.8x less crossbar traffic per FLOP).
//   CTA = 128 queries, 128 threads; grid (S/128, H, B) = 512 CTAs.
//   smem: Ks[64] Vs[64] Ps[128] rows (stride FS) = 69.6 KB; 2 CTAs/SM.
// ---------------------------------------------------------------------------
#define FS 68
#define FLASH_SMEM (256 * FS * 4)

__global__ __launch_bounds__(128, 2) void flash_mma()
{
    extern __shared__ float sm[];
    float* Ks = sm;                    //  64 rows
    float* Vs = sm + 64 * FS;          //  64 rows
    float* Ps = sm + 128 * FS;         // 128 rows (also Q staging)

    const int q0   = blockIdx.x * 128;
    const int h    = blockIdx.y;
    const int b    = blockIdx.z;
    const int tid  = threadIdx.x;
    const int wid  = tid >> 5;
    const int lane = tid & 31;
    const int r    = lane >> 2;
    const int q    = lane & 3;
    const int wrow = wid * 32;         // warp's 32-query base

    const float* Qb = g_qh + ((size_t)(b * HH + h) * SS) * HD;
    const float* Kb = g_kh + ((size_t)(b * HH + h) * SS) * HD;
    const float* Vb = g_vh + ((size_t)(b * HH + h) * SS) * HD;

    // stage Q (scaled, tf32) through Ps, extract A-fragments to registers
#pragma unroll
    for (int it = 0; it < 16; it++) {
        int lin = tid + it * 128;      // 2048 float4 slots (128 rows x 16)
        int row = lin >> 4;
        int c4  = lin & 15;
        float4 v = *(const float4*)&Qb[(size_t)(q0 + row) * HD + c4 * 4];
        v.x *= QK_SCALE; v.y *= QK_SCALE; v.z *= QK_SCALE; v.w *= QK_SCALE;
        *(float4*)&Ps[row * FS + c4 * 4] = to_tf32_4(v);
    }
    __syncthreads();

    float qf[2][8][4];
#pragma unroll
    for (int mt = 0; mt < 2; mt++)
#pragma unroll
        for (int ks = 0; ks < 8; ks++) {
            int row = wrow + mt * 16 + r;
            qf[mt][ks][0] = Ps[row * FS + ks * 8 + q];
            qf[mt][ks][1] = Ps[(row + 8) * FS + ks * 8 + q];
            qf[mt][ks][2] = Ps[row * FS + ks * 8 + q + 4];
            qf[mt][ks][3] = Ps[(row + 8) * FS + ks * 8 + q + 4];
        }
    __syncthreads();

    float o[2][8][4];
#pragma unroll
    for (int mt = 0; mt < 2; mt++)
#pragma unroll
        for (int j = 0; j < 8; j++)
#pragma unroll
            for (int c = 0; c < 4; c++) o[mt][j][c] = 0.f;
    float mx[2][2], ll[2][2];
#pragma unroll
    for (int mt = 0; mt < 2; mt++) {
        mx[mt][0] = -1e30f; mx[mt][1] = -1e30f;
        ll[mt][0] = 0.f;    ll[mt][1] = 0.f;
    }

    for (int kt = 0; kt < SS / 64; kt++) {
        const float* Kt = Kb + (size_t)(kt * 64) * HD;
        const float* Vt = Vb + (size_t)(kt * 64) * HD;

        // load K and V tiles (plain layout, STS.128)
#pragma unroll
        for (int it = 0; it < 8; it++) {
            int lin = tid + it * 128;
            int row = lin >> 4;
            int c4  = lin & 15;
            *(float4*)&Ks[row * FS + c4 * 4] =
                to_tf32_4(*(const float4*)&Kt[(size_t)row * HD + c4 * 4]);
            *(float4*)&Vs[row * FS + c4 * 4] =
                to_tf32_4(*(const float4*)&Vt[(size_t)row * HD + c4 * 4]);
        }
        __syncthreads();

        // ---- S = Q K^T : B-fragments loaded once, used by both m-tiles
        float s[2][8][4];
#pragma unroll
        for (int mt = 0; mt < 2; mt++)
#pragma unroll
            for (int j = 0; j < 8; j++)
#pragma unroll
                for (int c = 0; c < 4; c++) s[mt][j][c] = 0.f;

#pragma unroll
        for (int ks = 0; ks < 8; ks++) {
#pragma unroll
            for (int j = 0; j < 8; j++) {
                float bfr[2];
                bfr[0] = Ks[(j * 8 + r) * FS + ks * 8 + q];
                bfr[1] = Ks[(j * 8 + r) * FS + ks * 8 + q + 4];
                mma_tf32(s[0][j], qf[0][ks], bfr);
                mma_tf32(s[1][j], qf[1][ks], bfr);
            }
        }

        // ---- online softmax per m-tile (quad reduce)
        float corr[2][2];
#pragma unroll
        for (int mt = 0; mt < 2; mt++) {
            float t0 = -1e30f, t1 = -1e30f;
#pragma unroll
            for (int j = 0; j < 8; j++) {
                t0 = fmaxf(t0, fmaxf(s[mt][j][0], s[mt][j][1]));
                t1 = fmaxf(t1, fmaxf(s[mt][j][2], s[mt][j][3]));
            }
#pragma unroll
            for (int msk = 1; msk <= 2; msk <<= 1) {
                t0 = fmaxf(t0, __shfl_xor_sync(0xffffffffu, t0, msk));
                t1 = fmaxf(t1, __shfl_xor_sync(0xffffffffu, t1, msk));
            }
            float nm0 = fmaxf(mx[mt][0], t0), nm1 = fmaxf(mx[mt][1], t1);
            corr[mt][0] = __expf(mx[mt][0] - nm0);
            corr[mt][1] = __expf(mx[mt][1] - nm1);
            mx[mt][0] = nm0; mx[mt][1] = nm1;

            float rs0 = 0.f, rs1 = 0.f;
#pragma unroll
            for (int j = 0; j < 8; j++) {
                s[mt][j][0] = __expf(s[mt][j][0] - nm0);
                s[mt][j][1] = __expf(s[mt][j][1] - nm0);
                s[mt][j][2] = __expf(s[mt][j][2] - nm1);
                s[mt][j][3] = __expf(s[mt][j][3] - nm1);
                rs0 += s[mt][j][0] + s[mt][j][1];
                rs1 += s[mt][j][2] + s[mt][j][3];
            }
#pragma unroll
            for (int msk = 1; msk <= 2; msk <<= 1) {
                rs0 += __shfl_xor_sync(0xffffffffu, rs0, msk);
                rs1 += __shfl_xor_sync(0xffffffffu, rs1, msk);
            }
            ll[mt][0] = ll[mt][0] * corr[mt][0] + rs0;
            ll[mt][1] = ll[mt][1] * corr[mt][1] + rs1;

            // stage P rows for this m-tile (intra-warp only)
            int row = wrow + mt * 16 + r;
#pragma unroll
            for (int j = 0; j < 8; j++) {
                *(float2*)&Ps[row * FS + j * 8 + 2 * q] =
                    make_float2(to_tf32(s[mt][j][0]), to_tf32(s[mt][j][1]));
                *(float2*)&Ps[(row + 8) * FS + j * 8 + 2 * q] =
                    make_float2(to_tf32(s[mt][j][2]), to_tf32(s[mt][j][3]));
            }

            // rescale O
#pragma unroll
            for (int j = 0; j < 8; j++) {
                o[mt][j][0] *= corr[mt][0]; o[mt][j][1] *= corr[mt][0];
                o[mt][j][2] *= corr[mt][1]; o[mt][j][3] *= corr[mt][1];
            }
        }
        __syncwarp();

        // ---- O += P @ V : V B-fragments shared by both m-tiles
#pragma unroll
        for (int ks = 0; ks < 8; ks++) {
            float a[2][4];
#pragma unroll
            for (int mt = 0; mt < 2; mt++) {
                int row = wrow + mt * 16 + r;
                a[mt][0] = Ps[row * FS + ks * 8 + q];
                a[mt][1] = Ps[(row + 8) * FS + ks * 8 + q];
                a[mt][2] = Ps[row * FS + ks * 8 + q + 4];
                a[mt][3] = Ps[(row + 8) * FS + ks * 8 + q + 4];
            }
#pragma unroll
            for (int j = 0; j < 8; j++) {
                float bfr[2];
                bfr[0] = Vs[(ks * 8 + q) * FS + j * 8 + r];
                bfr[1] = Vs[(ks * 8 + q + 4) * FS + j * 8 + r];
                mma_tf32(o[0][j], a[0], bfr);
                mma_tf32(o[1][j], a[1], bfr);
            }
        }
        __syncthreads();   // Ks/Vs reads done before next tile load
    }

    // epilogue: normalize, write g_ao [B,S,D] (D col = h*64 + n)
#pragma unroll
    for (int mt = 0; mt < 2; mt++) {
        float inv0 = 1.f / ll[mt][0], inv1 = 1.f / ll[mt][1];
        int s0 = q0 + wrow + mt * 16 + r;
#pragma unroll
        for (int j = 0; j < 8; j++) {
            int col = h * HD + j * 8 + 2 * q;
            float* d0 = g_ao + ((size_t)b * SS + s0) * DD + col;
            *(float2*)d0 = make_float2(o[mt][j][0] * inv0, o[mt][j][1] * inv0);
            float* d1 = g_ao + ((size_t)b * SS + s0 + 8) * DD + col;
            *(float2*)d1 = make_float2(o[mt][j][2] * inv1, o[mt][j][3] * inv1);
        }
    }
}

// ---------------------------------------------------------------------------
extern "C" void kernel_launch(void* const* d_in, const int* in_sizes, int n_in,
                              void* d_out, int out_size)
{
    const float* q  = (const float*)d_in[0];
    const float* k  = (const float*)d_in[1];
    const float* v  = (const float*)d_in[2];
    const float* Wq = (const float*)d_in[3];
    const float* bq = (const float*)d_in[4];
    const float* Wk = (const float*)d_in[5];
    const float* bk = (const float*)d_in[6];
    const float* Wv = (const float*)d_in[7];
    const float* bv = (const float*)d_in[8];
    const float* Wo = (const float*)d_in[9];
    const float* bo = (const float*)d_in[10];
    float* out = (float*)d_out;

    cudaFuncSetAttribute(flash_mma,
                         cudaFuncAttributeMaxDynamicSharedMemorySize, FLASH_SMEM);

    dim3 pgrid(DD / 128, (BB * SS) / 128);   // (8, 32)
    proj_mma<0><<<pgrid, 256>>>(q, Wq, bq, nullptr);
    proj_mma<1><<<pgrid, 256>>>(k, Wk, bk, nullptr);
    proj_mma<2><<<pgrid, 256>>>(v, Wv, bv, nullptr);

    flash_mma<<<dim3(SS / 128, HH, BB), 128, FLASH_SMEM>>>();

    void* p_ao = nullptr;
    cudaGetSymbolAddress(&p_ao, g_ao);
    proj_mma<3><<<pgrid, 256>>>((const float*)p_ao, Wo, bo, out);
}